// round 5
// baseline (speedup 1.0000x reference)
#include <cuda_runtime.h>
#include <cuda_bf16.h>
#include <cstdint>

// AFM forward, algebraically collapsed (softmax over size-1 axis == 1):
//   x[b]   = 0.5*(||sum_f emb_f||^2 - sum_f ||emb_f||^2)
//   out[b] = sigmoid(x[b]*out_kernel + out_bias)
//
// Shape: TWO WARPS PER ROW (half-warp-per-13-fields).
//   8192 warps -> ~55 warps/SM (occ ~85%), vs 27.7 for warp-per-row.
//   Warp half h owns fields 13h..13h+12: 2 rounds of (<=8 fields x 4 slices).
//   <=2 direct id loads + <=2 16B gathers per lane (ids broadcast 4-lane).
//   Row's warp pair combines via a per-row NAMED barrier (bar.sync id,64),
//   not __syncthreads -- no block-wide convoying on the slowest gather.

#define B_ROWS   4096
#define N_SPARSE 26
#define VOCAB    100000

__global__ void __launch_bounds__(256) afm_gather_kernel(
    const int*    __restrict__ ids,     // [B, 26]
    const float4* __restrict__ table,   // [26, VOCAB, 4] float4 units
    const float*  __restrict__ out_k,   // [1]
    const float*  __restrict__ out_b,   // [1]
    float*        __restrict__ out)     // [B]
{
    const unsigned FULL = 0xffffffffu;

    __shared__ float4 sS[4][4];   // [row_in_block][slice]  half-1 partial S
    __shared__ float  sQ[4][4];   // [row_in_block][slice]  half-1 partial q

    const int tid   = threadIdx.x;
    const int warp  = tid >> 5;          // 0..7
    const int lane  = tid & 31;
    const int rib   = warp >> 1;         // row in block 0..3
    const int half  = warp & 1;          // which 13-field half
    const int row   = blockIdx.x * 4 + rib;

    const int slice = lane & 3;          // which float4 of the 16-float emb
    const int fg    = lane >> 2;         // field slot 0..7 within round

    const int* rid = ids + row * N_SPARSE + half * 13;

    float4 S = make_float4(0.f, 0.f, 0.f, 0.f);
    float  q = 0.f;

    // Round 0: fields 13h+0..7 (all fg). Round 1: fields 13h+8..12 (fg<5).
    #pragma unroll
    for (int r = 0; r < 2; ++r) {
        const int  fl  = r * 8 + fg;
        const bool act = (fl < 13);
        if (act) {
            const int id = __ldg(rid + fl);            // 4-lane broadcast
            const int f  = half * 13 + fl;
            const float4 v = __ldg(table + (size_t)f * (VOCAB * 4)
                                         + (size_t)id * 4 + slice);
            S.x += v.x; S.y += v.y; S.z += v.z; S.w += v.w;
            q   += v.x * v.x + v.y * v.y + v.z * v.z + v.w * v.w;
        }
    }

    // Reduce over the field slots (lane bits 2,3,4): 3 levels.
    #pragma unroll
    for (int d = 4; d <= 16; d <<= 1) {
        S.x += __shfl_xor_sync(FULL, S.x, d);
        S.y += __shfl_xor_sync(FULL, S.y, d);
        S.z += __shfl_xor_sync(FULL, S.z, d);
        S.w += __shfl_xor_sync(FULL, S.w, d);
        q   += __shfl_xor_sync(FULL, q, d);
    }
    // Lanes 0..3 hold this half's per-slice S (float4) and q partials.

    if (half == 1 && lane < 4) {
        sS[rib][lane] = S;
        sQ[rib][lane] = q;
    }
    // Per-row named barrier: only this row's two warps (64 threads).
    asm volatile("bar.sync %0, %1;" :: "r"(rib + 1), "r"(64) : "memory");

    if (half == 0 && lane < 4) {
        const float4 P = sS[rib][lane];
        float4 St = make_float4(S.x + P.x, S.y + P.y, S.z + P.z, S.w + P.w);
        float  qt = q + sQ[rib][lane];
        float  s2 = St.x * St.x + St.y * St.y + St.z * St.z + St.w * St.w;
        // Sum s2 and qt over the 4 slice lanes.
        s2 += __shfl_xor_sync(0xFu, s2, 1); s2 += __shfl_xor_sync(0xFu, s2, 2);
        qt += __shfl_xor_sync(0xFu, qt, 1); qt += __shfl_xor_sync(0xFu, qt, 2);
        if (lane == 0) {
            const float t = s2 - qt;             // == 2 * sum_{i<j} e_i.e_j
            const float z = 0.5f * t * __ldg(out_k) + __ldg(out_b);
            out[row] = 1.0f / (1.0f + __expf(-z));
        }
    }
}

extern "C" void kernel_launch(void* const* d_in, const int* in_sizes, int n_in,
                              void* d_out, int out_size)
{
    (void)in_sizes; (void)n_in; (void)out_size;
    const int*    ids   = (const int*)   d_in[1];
    const float4* table = (const float4*)d_in[2];
    const float*  out_k = (const float*) d_in[7];
    const float*  out_b = (const float*) d_in[8];
    float*        out   = (float*)       d_out;

    const int threads = 256;             // 8 warps = 4 rows per block
    const int blocks  = B_ROWS / 4;      // 1024 blocks
    afm_gather_kernel<<<blocks, threads>>>(ids, table, out_k, out_b, out);
}

// round 6
// speedup vs baseline: 1.3023x; 1.3023x over previous
#include <cuda_runtime.h>
#include <cuda_bf16.h>
#include <cstdint>

// AFM forward, algebraically collapsed (softmax over size-1 axis == 1):
//   x[b]   = 0.5*(||sum_f emb_f||^2 - sum_f ||emb_f||^2)
//   out[b] = sigmoid(x[b]*out_kernel + out_bias)
//
// Shape: ONE WARP PER ROW (best measured across R1-R5), launched as
// EXACTLY 148 CTAs x 28 warps so every SM gets ONE CTA and 27-28 rows.
// R4's 256x16 launch put 32 warps on 108 SMs and 16 on the other 40
// (2x memory-work skew); this launch is perfectly balanced, one wave.
// Per lane: <=4 direct broadcast id loads + <=4 independent 16B gathers,
// then a 3-level in-warp shuffle reduction. No smem, no barriers.

#define B_ROWS   4096
#define N_SPARSE 26
#define VOCAB    100000
#define NSM      148
#define WARPS_PER_CTA 28   // 148*28 = 4144 >= 4096

__global__ void __launch_bounds__(WARPS_PER_CTA * 32) afm_gather_kernel(
    const int*    __restrict__ ids,     // [B, 26]
    const float4* __restrict__ table,   // [26, VOCAB, 4] float4 units
    const float*  __restrict__ out_k,   // [1]
    const float*  __restrict__ out_b,   // [1]
    float*        __restrict__ out)     // [B]
{
    const unsigned FULL = 0xffffffffu;
    const int warp = threadIdx.x >> 5;
    const int lane = threadIdx.x & 31;
    const int row  = blockIdx.x * WARPS_PER_CTA + warp;  // one warp per row
    if (row >= B_ROWS) return;

    const int slice = lane & 3;          // which float4 of the 16-float emb
    const int fg    = lane >> 2;         // field-in-group 0..7

    const int* rid = ids + row * N_SPARSE;

    // Round r handles field f = r*8 + fg (round 3: fg 0,1 only).
    // id loads are 4-lane broadcasts; every gather depends only on its id,
    // so all 4 id LDGs + 4 gather LDGs front-batch (MLP ~8 per lane).
    float4 S = make_float4(0.f, 0.f, 0.f, 0.f);
    float  q = 0.f;

    #pragma unroll
    for (int r = 0; r < 4; ++r) {
        const int  f   = r * 8 + fg;
        const bool act = (f < N_SPARSE);
        if (act) {
            const int id = __ldg(rid + f);
            const float4 v = __ldg(table + (size_t)f * (VOCAB * 4)
                                         + (size_t)id * 4 + slice);
            S.x += v.x; S.y += v.y; S.z += v.z; S.w += v.w;
            q   += v.x * v.x + v.y * v.y + v.z * v.z + v.w * v.w;
        }
    }

    // Reduce S and q over the field dimension (lane bits 2,3,4).
    #pragma unroll
    for (int d = 4; d <= 16; d <<= 1) {
        S.x += __shfl_xor_sync(FULL, S.x, d);
        S.y += __shfl_xor_sync(FULL, S.y, d);
        S.z += __shfl_xor_sync(FULL, S.z, d);
        S.w += __shfl_xor_sync(FULL, S.w, d);
        q   += __shfl_xor_sync(FULL, q, d);
    }

    // Lanes 0..3 hold per-slice totals: |S|^2 per slice, then sum slices.
    float s2 = S.x * S.x + S.y * S.y + S.z * S.z + S.w * S.w;
    s2 += __shfl_xor_sync(FULL, s2, 1);
    s2 += __shfl_xor_sync(FULL, s2, 2);
    q  += __shfl_xor_sync(FULL, q, 1);
    q  += __shfl_xor_sync(FULL, q, 2);

    if (lane == 0) {
        const float t = s2 - q;                  // == 2 * sum_{i<j} e_i.e_j
        const float z = 0.5f * t * __ldg(out_k) + __ldg(out_b);
        out[row] = 1.0f / (1.0f + __expf(-z));
    }
}

extern "C" void kernel_launch(void* const* d_in, const int* in_sizes, int n_in,
                              void* d_out, int out_size)
{
    (void)in_sizes; (void)n_in; (void)out_size;
    const int*    ids   = (const int*)   d_in[1];
    const float4* table = (const float4*)d_in[2];
    const float*  out_k = (const float*) d_in[7];
    const float*  out_b = (const float*) d_in[8];
    float*        out   = (float*)       d_out;

    afm_gather_kernel<<<NSM, WARPS_PER_CTA * 32>>>(ids, table, out_k, out_b, out);
}

// round 7
// speedup vs baseline: 1.3527x; 1.0386x over previous
#include <cuda_runtime.h>
#include <cuda_bf16.h>
#include <cstdint>

// AFM forward, algebraically collapsed (softmax over size-1 axis == 1):
//   x[b]   = 0.5*(||sum_f emb_f||^2 - sum_f ||emb_f||^2)
//   out[b] = sigmoid(x[b]*out_kernel + out_bias)
//
// Shape: ONE WARP PER ROW, 256 CTAs x 512 threads (best measured: R4).
// Change vs R4: all 4 id loads are issued UNCONDITIONALLY up-front with a
// clamped field index (min(f,25) stays inside the row), so SASS is a clean
// front-batch: 4 id LDGs -> 4 gather LDGs (MLP_p1=8, two-level chain).
// The out-of-range gathers stay predicated off (no extra 64B traffic).

#define B_ROWS   4096
#define N_SPARSE 26
#define VOCAB    100000

__global__ void __launch_bounds__(512) afm_gather_kernel(
    const int*    __restrict__ ids,     // [B, 26]
    const float4* __restrict__ table,   // [26, VOCAB, 4] float4 units
    const float*  __restrict__ out_k,   // [1]
    const float*  __restrict__ out_b,   // [1]
    float*        __restrict__ out)     // [B]
{
    const unsigned FULL = 0xffffffffu;
    const int gtid = blockIdx.x * blockDim.x + threadIdx.x;
    const int row  = gtid >> 5;            // one warp per row (grid exact)
    const int lane = threadIdx.x & 31;

    const int slice = lane & 3;            // float4 slice of the embedding
    const int fg    = lane >> 2;           // field-in-group 0..7

    const int* rid = ids + row * N_SPARSE;

    // Scalar params hoisted off the tail's critical path.
    const float okv = __ldg(out_k);
    const float obv = __ldg(out_b);

    // Front-batched id loads: unconditional, clamped in-row (4-lane bcast,
    // 32B per warp per round; round 3 duplicates field 25 for fg>=2 but its
    // gather is predicated off below).
    int idr[4];
    #pragma unroll
    for (int r = 0; r < 4; ++r) {
        int f = r * 8 + fg;
        idr[r] = __ldg(rid + (f < N_SPARSE ? f : N_SPARSE - 1));
    }

    float4 S = make_float4(0.f, 0.f, 0.f, 0.f);
    float  q = 0.f;

    #pragma unroll
    for (int r = 0; r < 4; ++r) {
        const int f = r * 8 + fg;
        if (f < N_SPARSE) {
            const float4 v = __ldg(table + (size_t)f * (VOCAB * 4)
                                         + (size_t)idr[r] * 4 + slice);
            S.x += v.x; S.y += v.y; S.z += v.z; S.w += v.w;
            q   += v.x * v.x + v.y * v.y + v.z * v.z + v.w * v.w;
        }
    }

    // Reduce S and q over the field dimension (lane bits 2,3,4).
    #pragma unroll
    for (int d = 4; d <= 16; d <<= 1) {
        S.x += __shfl_xor_sync(FULL, S.x, d);
        S.y += __shfl_xor_sync(FULL, S.y, d);
        S.z += __shfl_xor_sync(FULL, S.z, d);
        S.w += __shfl_xor_sync(FULL, S.w, d);
        q   += __shfl_xor_sync(FULL, q, d);
    }

    // Lanes 0..3 hold per-slice totals: |S|^2 per slice, then sum slices.
    float s2 = S.x * S.x + S.y * S.y + S.z * S.z + S.w * S.w;
    s2 += __shfl_xor_sync(FULL, s2, 1);
    s2 += __shfl_xor_sync(FULL, s2, 2);
    q  += __shfl_xor_sync(FULL, q, 1);
    q  += __shfl_xor_sync(FULL, q, 2);

    if (lane == 0) {
        const float t = s2 - q;                  // == 2 * sum_{i<j} e_i.e_j
        const float z = 0.5f * t * okv + obv;
        out[row] = 1.0f / (1.0f + __expf(-z));
    }
}

extern "C" void kernel_launch(void* const* d_in, const int* in_sizes, int n_in,
                              void* d_out, int out_size)
{
    (void)in_sizes; (void)n_in; (void)out_size;
    const int*    ids   = (const int*)   d_in[1];
    const float4* table = (const float4*)d_in[2];
    const float*  out_k = (const float*) d_in[7];
    const float*  out_b = (const float*) d_in[8];
    float*        out   = (float*)       d_out;

    const int threads = 512;                     // 16 warps = 16 rows / block
    const int blocks  = (B_ROWS * 32) / threads; // 256 blocks, exact
    afm_gather_kernel<<<blocks, threads>>>(ids, table, out_k, out_b, out);
}